// round 2
// baseline (speedup 1.0000x reference)
#include <cuda_runtime.h>
#include <cstdint>

#define Lq   4096
#define DIN  512
#define DOUTC 256
#define NH   4
#define HD   64
#define TI   32      // rows per CTA in attention kernel
#define CJ   64      // j-chunk

// ---------------- scratch (device globals; no allocs allowed) ----------------
__device__ float g_Wh[Lq * DOUTC];    // 4 MB
__device__ float g_si[Lq * NH];
__device__ float g_sj[Lq * NH];
__device__ float g_att[Lq * DOUTC];   // 4 MB

__device__ __forceinline__ float lrelu(float x) { return fmaxf(x, 0.2f * x); }

__device__ __forceinline__ unsigned long long pack2(float x, float y) {
    unsigned long long r;
    asm("mov.b64 %0, {%1, %2};" : "=l"(r) : "f"(x), "f"(y));
    return r;
}
__device__ __forceinline__ void fma2(unsigned long long& d,
                                     unsigned long long a,
                                     unsigned long long b) {
    asm("fma.rn.f32x2 %0, %1, %2, %0;" : "+l"(d) : "l"(a), "l"(b));
}
__device__ __forceinline__ float2 unpack2(unsigned long long v) {
    float2 f;
    asm("mov.b64 {%0, %1}, %2;" : "=f"(f.x), "=f"(f.y) : "l"(v));
    return f;
}

// ---------------- generic 64x64-tile fp32 GEMM: C = A @ B^T (+bias) ----------
// MODE 0: A = Aext (h),    C = g_Wh,  no bias      (K = DIN)
// MODE 1: A = g_att,       C = Cext,  bias = out_b (K = DOUTC)
template <int K, int MODE>
__global__ void __launch_bounds__(256) gemm64_nt(const float* __restrict__ Aext,
                                                 const float* __restrict__ Bm,
                                                 float* __restrict__ Cext,
                                                 const float* __restrict__ bias) {
    __shared__ float As[16][68];
    __shared__ float Bs[16][68];
    const float* Am = (MODE == 0) ? Aext : g_att;
    float*       Cm = (MODE == 0) ? g_Wh : Cext;

    int tid = threadIdx.x;
    int m0 = blockIdx.y * 64, n0 = blockIdx.x * 64;
    int tx = tid & 15, ty = tid >> 4;

    float acc[4][4] = {};
    int r  = tid >> 2;
    int kk = (tid & 3) * 4;

    for (int k0 = 0; k0 < K; k0 += 16) {
        float4 av = *(const float4*)&Am[(size_t)(m0 + r) * K + k0 + kk];
        As[kk + 0][r] = av.x; As[kk + 1][r] = av.y;
        As[kk + 2][r] = av.z; As[kk + 3][r] = av.w;
        float4 bv = *(const float4*)&Bm[(size_t)(n0 + r) * K + k0 + kk];
        Bs[kk + 0][r] = bv.x; Bs[kk + 1][r] = bv.y;
        Bs[kk + 2][r] = bv.z; Bs[kk + 3][r] = bv.w;
        __syncthreads();
#pragma unroll
        for (int k = 0; k < 16; k++) {
            float a[4], b[4];
            *(float4*)a = *(const float4*)&As[k][ty * 4];
            *(float4*)b = *(const float4*)&Bs[k][tx * 4];
#pragma unroll
            for (int i = 0; i < 4; i++)
#pragma unroll
                for (int j = 0; j < 4; j++)
                    acc[i][j] += a[i] * b[j];
        }
        __syncthreads();
    }

    float4 bv = make_float4(0.f, 0.f, 0.f, 0.f);
    if (MODE == 1) bv = *(const float4*)&bias[n0 + tx * 4];
#pragma unroll
    for (int i = 0; i < 4; i++) {
        float4 o = make_float4(acc[i][0] + bv.x, acc[i][1] + bv.y,
                               acc[i][2] + bv.z, acc[i][3] + bv.w);
        *(float4*)&Cm[(size_t)(m0 + ty * 4 + i) * DOUTC + n0 + tx * 4] = o;
    }
}

// ---------------- s_i / s_j: per (l, h) dot with a1/a2 -----------------------
__global__ void __launch_bounds__(256) s_kernel(const float* __restrict__ attn) {
    int gw = blockIdx.x * 8 + (threadIdx.x >> 5);
    int lane = threadIdx.x & 31;
    int l = gw >> 2, hh = gw & 3;
    const float* whp = &g_Wh[(size_t)l * DOUTC + hh * HD];
    float v0 = whp[lane], v1 = whp[lane + 32];
    const float* ap = &attn[hh * 2 * HD];
    float si = v0 * ap[lane]      + v1 * ap[lane + 32];
    float sj = v0 * ap[64 + lane] + v1 * ap[96 + lane];
#pragma unroll
    for (int o = 16; o; o >>= 1) {
        si += __shfl_xor_sync(0xffffffffu, si, o);
        sj += __shfl_xor_sync(0xffffffffu, sj, o);
    }
    if (lane == 0) { g_si[l * NH + hh] = si; g_sj[l * NH + hh] = sj; }
}

// ---------------- fused masked-softmax aggregation ---------------------------
// smem layout:
//   sj4    : float4[4096]                    65536 B
//   w_s    : float [4][CJ][34]               34816 B
//   mask_s : uint32[TI][128]                 16384 B
//   si_s, m_s, rd_s : float4[TI] each         1536 B
#define SM_SJ   0
#define SM_W    65536
#define SM_MASK (65536 + 34816)
#define SM_SI   (65536 + 34816 + 16384)
#define SM_M    (SM_SI + TI * 16)
#define SM_RD   (SM_M + TI * 16)
#define SM_TOT  (SM_RD + TI * 16)

__global__ void __launch_bounds__(256) gat_attn_kernel(const int* __restrict__ A) {
    extern __shared__ char smem[];
    float4*   sj4    = (float4*)(smem + SM_SJ);
    float*    w_s    = (float*)(smem + SM_W);
    uint32_t* mask_s = (uint32_t*)(smem + SM_MASK);
    float4*   si_s   = (float4*)(smem + SM_SI);
    float4*   m_s    = (float4*)(smem + SM_M);
    float4*   rd_s   = (float4*)(smem + SM_RD);

    int tid = threadIdx.x, lane = tid & 31, wid = tid >> 5;
    int i0 = blockIdx.x * TI;

    // stage s_j (full) and s_i (block rows)
    for (int j = tid; j < Lq; j += 256) sj4[j] = ((const float4*)g_sj)[j];
    if (tid < TI) si_s[tid] = ((const float4*)g_si)[i0 + tid];

    // adjacency bitmask via ballot (A read exactly once, coalesced)
    for (int ii = 0; ii < TI; ii++) {
        const int* Arow = A + (size_t)(i0 + ii) * Lq;
#pragma unroll
        for (int t = 0; t < Lq / 256; t++) {
            int j = (t * 8 + wid) * 32 + lane;
            uint32_t b = __ballot_sync(0xffffffffu, Arow[j] > 0);
            if (lane == 0) mask_s[ii * 128 + t * 8 + wid] = b;
        }
    }
    __syncthreads();

    // phase 1: per-row m and 1/denom (lrelu monotone -> m = lrelu(si + max sj))
    for (int rr = wid; rr < TI; rr += 8) {
        float4 si = si_s[rr];
        float mx0 = -1e30f, mx1 = -1e30f, mx2 = -1e30f, mx3 = -1e30f;
        for (int t = 0; t < 128; t++) {
            uint32_t word = mask_s[rr * 128 + t];
            if (word & (1u << lane)) {
                float4 s = sj4[t * 32 + lane];
                mx0 = fmaxf(mx0, s.x); mx1 = fmaxf(mx1, s.y);
                mx2 = fmaxf(mx2, s.z); mx3 = fmaxf(mx3, s.w);
            }
        }
#pragma unroll
        for (int o = 16; o; o >>= 1) {
            mx0 = fmaxf(mx0, __shfl_xor_sync(0xffffffffu, mx0, o));
            mx1 = fmaxf(mx1, __shfl_xor_sync(0xffffffffu, mx1, o));
            mx2 = fmaxf(mx2, __shfl_xor_sync(0xffffffffu, mx2, o));
            mx3 = fmaxf(mx3, __shfl_xor_sync(0xffffffffu, mx3, o));
        }
        bool has = mx0 > -1e29f;
        float m0 = has ? lrelu(si.x + mx0) : 0.f;
        float m1 = has ? lrelu(si.y + mx1) : 0.f;
        float m2 = has ? lrelu(si.z + mx2) : 0.f;
        float m3 = has ? lrelu(si.w + mx3) : 0.f;
        float s0 = 0.f, s1 = 0.f, s2 = 0.f, s3 = 0.f;
        for (int t = 0; t < 128; t++) {
            uint32_t word = mask_s[rr * 128 + t];
            if (word & (1u << lane)) {
                float4 s = sj4[t * 32 + lane];
                s0 += __expf(lrelu(si.x + s.x) - m0);
                s1 += __expf(lrelu(si.y + s.y) - m1);
                s2 += __expf(lrelu(si.z + s.z) - m2);
                s3 += __expf(lrelu(si.w + s.w) - m3);
            }
        }
#pragma unroll
        for (int o = 16; o; o >>= 1) {
            s0 += __shfl_xor_sync(0xffffffffu, s0, o);
            s1 += __shfl_xor_sync(0xffffffffu, s1, o);
            s2 += __shfl_xor_sync(0xffffffffu, s2, o);
            s3 += __shfl_xor_sync(0xffffffffu, s3, o);
        }
        if (lane == 0) {
            m_s[rr]  = make_float4(m0, m1, m2, m3);
            rd_s[rr] = make_float4(has ? 1.f / s0 : 0.f, has ? 1.f / s1 : 0.f,
                                   has ? 1.f / s2 : 0.f, has ? 1.f / s3 : 0.f);
        }
    }
    __syncthreads();

    // phase 2: chunked alpha @ Wh with f32x2 packed accumulators
    int iig  = tid >> 6;         // w-compute row group (0..3)
    int jj_w = tid & 63;
    int cq   = tid & 63;         // col quad (4 cols)
    int hA   = cq >> 4;          // head of this thread's cols
    int r0   = iig * 8;          // accumulate row base
    unsigned long long acc[4][4];
#pragma unroll
    for (int a = 0; a < 4; a++)
#pragma unroll
        for (int b = 0; b < 4; b++) acc[a][b] = 0ull;

    const float4* Wh4 = (const float4*)g_Wh;

    for (int j0 = 0; j0 < Lq; j0 += CJ) {
        // compute alpha chunk into smem
        {
            int j = j0 + jj_w;
            float4 s = sj4[j];
            uint32_t sel = 1u << (j & 31);
            int wo = j >> 5;
#pragma unroll
            for (int k = 0; k < 8; k++) {
                int ii = iig * 8 + k;
                float w0 = 0.f, w1 = 0.f, w2 = 0.f, w3 = 0.f;
                if (mask_s[ii * 128 + wo] & sel) {
                    float4 si = si_s[ii], mm = m_s[ii], rd = rd_s[ii];
                    w0 = __expf(lrelu(si.x + s.x) - mm.x) * rd.x;
                    w1 = __expf(lrelu(si.y + s.y) - mm.y) * rd.y;
                    w2 = __expf(lrelu(si.z + s.z) - mm.z) * rd.z;
                    w3 = __expf(lrelu(si.w + s.w) - mm.w) * rd.w;
                }
                w_s[(0 * CJ + jj_w) * 34 + ii] = w0;
                w_s[(1 * CJ + jj_w) * 34 + ii] = w1;
                w_s[(2 * CJ + jj_w) * 34 + ii] = w2;
                w_s[(3 * CJ + jj_w) * 34 + ii] = w3;
            }
        }
        __syncthreads();

        const float*  wbase = w_s + hA * CJ * 34 + r0;
        const float4* whp   = Wh4 + (size_t)j0 * 64 + cq;
#pragma unroll 4
        for (int jj = 0; jj < CJ; jj++) {
            float4 wh = whp[(size_t)jj * 64];
            unsigned long long bx = pack2(wh.x, wh.x);
            unsigned long long by = pack2(wh.y, wh.y);
            unsigned long long bz = pack2(wh.z, wh.z);
            unsigned long long bw = pack2(wh.w, wh.w);
            const float* wp = wbase + jj * 34;
            unsigned long long w01 = *(const unsigned long long*)(wp + 0);
            unsigned long long w23 = *(const unsigned long long*)(wp + 2);
            unsigned long long w45 = *(const unsigned long long*)(wp + 4);
            unsigned long long w67 = *(const unsigned long long*)(wp + 6);
            fma2(acc[0][0], w01, bx); fma2(acc[0][1], w01, by);
            fma2(acc[0][2], w01, bz); fma2(acc[0][3], w01, bw);
            fma2(acc[1][0], w23, bx); fma2(acc[1][1], w23, by);
            fma2(acc[1][2], w23, bz); fma2(acc[1][3], w23, bw);
            fma2(acc[2][0], w45, bx); fma2(acc[2][1], w45, by);
            fma2(acc[2][2], w45, bz); fma2(acc[2][3], w45, bw);
            fma2(acc[3][0], w67, bx); fma2(acc[3][1], w67, by);
            fma2(acc[3][2], w67, bz); fma2(acc[3][3], w67, bw);
        }
        __syncthreads();
    }

    // writeback (unpack row pairs)
#pragma unroll
    for (int kp = 0; kp < 4; kp++) {
        float2 c0 = unpack2(acc[kp][0]);
        float2 c1 = unpack2(acc[kp][1]);
        float2 c2 = unpack2(acc[kp][2]);
        float2 c3 = unpack2(acc[kp][3]);
        int row = i0 + r0 + kp * 2;
        *(float4*)&g_att[(size_t)row * DOUTC + cq * 4] =
            make_float4(c0.x, c1.x, c2.x, c3.x);
        *(float4*)&g_att[(size_t)(row + 1) * DOUTC + cq * 4] =
            make_float4(c0.y, c1.y, c2.y, c3.y);
    }
}

// ---------------- launch ------------------------------------------------------
extern "C" void kernel_launch(void* const* d_in, const int* in_sizes, int n_in,
                              void* d_out, int out_size) {
    const float* h     = (const float*)d_in[0];
    const int*   A     = (const int*)d_in[1];
    const float* W     = (const float*)d_in[2];
    const float* attn  = (const float*)d_in[3];
    const float* out_w = (const float*)d_in[4];
    const float* out_b = (const float*)d_in[5];
    float*       out   = (float*)d_out;

    // 1) Wh = h @ W^T
    gemm64_nt<DIN, 0><<<dim3(DOUTC / 64, Lq / 64), 256>>>(h, W, nullptr, nullptr);
    // 2) s_i, s_j
    s_kernel<<<(Lq * NH) / 8, 256>>>(attn);
    // 3) masked softmax + aggregation
    cudaFuncSetAttribute(gat_attn_kernel,
                         cudaFuncAttributeMaxDynamicSharedMemorySize, SM_TOT);
    gat_attn_kernel<<<Lq / TI, 256, SM_TOT>>>(A);
    // 4) out = att @ out_w^T + out_b
    gemm64_nt<DOUTC, 1><<<dim3(DOUTC / 64, Lq / 64), 256>>>(nullptr, out_w, out, out_b);
}

// round 3
// speedup vs baseline: 1.0759x; 1.0759x over previous
#include <cuda_runtime.h>
#include <cstdint>

#define Lq   4096
#define DIN  512
#define DOUTC 256
#define NH   4
#define HD   64
#define TI   16      // rows per CTA in attention kernel
#define CJ   64      // j-chunk

// ---------------- scratch (device globals; no allocs allowed) ----------------
__device__ float g_Wh[Lq * DOUTC];    // 4 MB
__device__ float g_si[Lq * NH];
__device__ float g_sj[Lq * NH];
__device__ float g_att[Lq * DOUTC];   // 4 MB

__device__ __forceinline__ float lrelu(float x) { return fmaxf(x, 0.2f * x); }

__device__ __forceinline__ unsigned long long pack2(float x, float y) {
    unsigned long long r;
    asm("mov.b64 %0, {%1, %2};" : "=l"(r) : "f"(x), "f"(y));
    return r;
}
__device__ __forceinline__ void fma2(unsigned long long& d,
                                     unsigned long long a,
                                     unsigned long long b) {
    asm("fma.rn.f32x2 %0, %1, %2, %0;" : "+l"(d) : "l"(a), "l"(b));
}
__device__ __forceinline__ float2 unpack2(unsigned long long v) {
    float2 f;
    asm("mov.b64 {%0, %1}, %2;" : "=f"(f.x), "=f"(f.y) : "l"(v));
    return f;
}

// ---------------- generic 64x64-tile fp32 GEMM: C = A @ B^T (+bias) ----------
// MODE 0: A = Aext (h),    C = g_Wh,  no bias      (K = DIN)
// MODE 1: A = g_att,       C = Cext,  bias = out_b (K = DOUTC)
template <int K, int MODE>
__global__ void __launch_bounds__(256) gemm64_nt(const float* __restrict__ Aext,
                                                 const float* __restrict__ Bm,
                                                 float* __restrict__ Cext,
                                                 const float* __restrict__ bias) {
    __shared__ float As[16][68];
    __shared__ float Bs[16][68];
    const float* Am = (MODE == 0) ? Aext : g_att;
    float*       Cm = (MODE == 0) ? g_Wh : Cext;

    int tid = threadIdx.x;
    int m0 = blockIdx.y * 64, n0 = blockIdx.x * 64;
    int tx = tid & 15, ty = tid >> 4;

    float acc[4][4] = {};
    int r  = tid >> 2;
    int kk = (tid & 3) * 4;

    for (int k0 = 0; k0 < K; k0 += 16) {
        float4 av = *(const float4*)&Am[(size_t)(m0 + r) * K + k0 + kk];
        As[kk + 0][r] = av.x; As[kk + 1][r] = av.y;
        As[kk + 2][r] = av.z; As[kk + 3][r] = av.w;
        float4 bv = *(const float4*)&Bm[(size_t)(n0 + r) * K + k0 + kk];
        Bs[kk + 0][r] = bv.x; Bs[kk + 1][r] = bv.y;
        Bs[kk + 2][r] = bv.z; Bs[kk + 3][r] = bv.w;
        __syncthreads();
#pragma unroll
        for (int k = 0; k < 16; k++) {
            float a[4], b[4];
            *(float4*)a = *(const float4*)&As[k][ty * 4];
            *(float4*)b = *(const float4*)&Bs[k][tx * 4];
#pragma unroll
            for (int i = 0; i < 4; i++)
#pragma unroll
                for (int j = 0; j < 4; j++)
                    acc[i][j] += a[i] * b[j];
        }
        __syncthreads();
    }

    float4 bv = make_float4(0.f, 0.f, 0.f, 0.f);
    if (MODE == 1) bv = *(const float4*)&bias[n0 + tx * 4];
#pragma unroll
    for (int i = 0; i < 4; i++) {
        float4 o = make_float4(acc[i][0] + bv.x, acc[i][1] + bv.y,
                               acc[i][2] + bv.z, acc[i][3] + bv.w);
        *(float4*)&Cm[(size_t)(m0 + ty * 4 + i) * DOUTC + n0 + tx * 4] = o;
    }
}

// ---------------- s_i / s_j: per (l, h) dot with a1/a2 -----------------------
__global__ void __launch_bounds__(256) s_kernel(const float* __restrict__ attn) {
    int gw = blockIdx.x * 8 + (threadIdx.x >> 5);
    int lane = threadIdx.x & 31;
    int l = gw >> 2, hh = gw & 3;
    const float* whp = &g_Wh[(size_t)l * DOUTC + hh * HD];
    float v0 = whp[lane], v1 = whp[lane + 32];
    const float* ap = &attn[hh * 2 * HD];
    float si = v0 * ap[lane]      + v1 * ap[lane + 32];
    float sj = v0 * ap[64 + lane] + v1 * ap[96 + lane];
#pragma unroll
    for (int o = 16; o; o >>= 1) {
        si += __shfl_xor_sync(0xffffffffu, si, o);
        sj += __shfl_xor_sync(0xffffffffu, sj, o);
    }
    if (lane == 0) { g_si[l * NH + hh] = si; g_sj[l * NH + hh] = sj; }
}

// ---------------- fused masked-softmax aggregation ---------------------------
// smem layout (no s_j stage — read from L1 via __ldg):
//   w_s    : float [4][CJ][34]               34816 B
//   mask_s : uint32[TI][128]                  8192 B
//   si_s, m_s, rd_s : float4[TI] each          768 B
#define SM_W    0
#define SM_MASK 34816
#define SM_SI   (34816 + 8192)
#define SM_M    (SM_SI + TI * 16)
#define SM_RD   (SM_M + TI * 16)
#define SM_TOT  (SM_RD + TI * 16)

__global__ void __launch_bounds__(256) gat_attn_kernel(const int* __restrict__ A) {
    extern __shared__ char smem[];
    float*    w_s    = (float*)(smem + SM_W);
    uint32_t* mask_s = (uint32_t*)(smem + SM_MASK);
    float4*   si_s   = (float4*)(smem + SM_SI);
    float4*   m_s    = (float4*)(smem + SM_M);
    float4*   rd_s   = (float4*)(smem + SM_RD);

    const float4* sjg = (const float4*)g_sj;

    int tid = threadIdx.x, lane = tid & 31, wid = tid >> 5;
    int i0 = blockIdx.x * TI;

    if (tid < TI) si_s[tid] = ((const float4*)g_si)[i0 + tid];

    // adjacency bitmask via ballot (A rows read exactly once, coalesced)
    for (int ii = 0; ii < TI; ii++) {
        const int* Arow = A + (size_t)(i0 + ii) * Lq;
#pragma unroll
        for (int t = 0; t < Lq / 256; t++) {
            int j = (t * 8 + wid) * 32 + lane;
            uint32_t b = __ballot_sync(0xffffffffu, Arow[j] > 0);
            if (lane == 0) mask_s[ii * 128 + t * 8 + wid] = b;
        }
    }
    __syncthreads();

    // phase 1: per-row m and 1/denom (lrelu monotone -> m = lrelu(si + max sj))
    for (int rr = wid; rr < TI; rr += 8) {
        float4 si = si_s[rr];
        float mx0 = -1e30f, mx1 = -1e30f, mx2 = -1e30f, mx3 = -1e30f;
        for (int t = 0; t < 128; t++) {
            uint32_t word = mask_s[rr * 128 + t];
            if (word & (1u << lane)) {
                float4 s = __ldg(&sjg[t * 32 + lane]);
                mx0 = fmaxf(mx0, s.x); mx1 = fmaxf(mx1, s.y);
                mx2 = fmaxf(mx2, s.z); mx3 = fmaxf(mx3, s.w);
            }
        }
#pragma unroll
        for (int o = 16; o; o >>= 1) {
            mx0 = fmaxf(mx0, __shfl_xor_sync(0xffffffffu, mx0, o));
            mx1 = fmaxf(mx1, __shfl_xor_sync(0xffffffffu, mx1, o));
            mx2 = fmaxf(mx2, __shfl_xor_sync(0xffffffffu, mx2, o));
            mx3 = fmaxf(mx3, __shfl_xor_sync(0xffffffffu, mx3, o));
        }
        bool has = mx0 > -1e29f;
        float m0 = has ? lrelu(si.x + mx0) : 0.f;
        float m1 = has ? lrelu(si.y + mx1) : 0.f;
        float m2 = has ? lrelu(si.z + mx2) : 0.f;
        float m3 = has ? lrelu(si.w + mx3) : 0.f;
        float s0 = 0.f, s1 = 0.f, s2 = 0.f, s3 = 0.f;
        for (int t = 0; t < 128; t++) {
            uint32_t word = mask_s[rr * 128 + t];
            if (word & (1u << lane)) {
                float4 s = __ldg(&sjg[t * 32 + lane]);
                s0 += __expf(lrelu(si.x + s.x) - m0);
                s1 += __expf(lrelu(si.y + s.y) - m1);
                s2 += __expf(lrelu(si.z + s.z) - m2);
                s3 += __expf(lrelu(si.w + s.w) - m3);
            }
        }
#pragma unroll
        for (int o = 16; o; o >>= 1) {
            s0 += __shfl_xor_sync(0xffffffffu, s0, o);
            s1 += __shfl_xor_sync(0xffffffffu, s1, o);
            s2 += __shfl_xor_sync(0xffffffffu, s2, o);
            s3 += __shfl_xor_sync(0xffffffffu, s3, o);
        }
        if (lane == 0) {
            m_s[rr]  = make_float4(m0, m1, m2, m3);
            rd_s[rr] = make_float4(has ? 1.f / s0 : 0.f, has ? 1.f / s1 : 0.f,
                                   has ? 1.f / s2 : 0.f, has ? 1.f / s3 : 0.f);
        }
    }
    __syncthreads();

    // phase 2: chunked alpha @ Wh with f32x2 packed accumulators
    // 256 threads = 4 row-groups (4 rows = 2 packed pairs) x 64 col-quads
    int iig  = tid >> 6;         // row group (0..3)
    int jj_w = tid & 63;
    int cq   = tid & 63;         // col quad (4 cols)
    int hA   = cq >> 4;          // head of this thread's cols
    int r0   = iig * 4;          // row base
    unsigned long long acc[2][4];
#pragma unroll
    for (int a = 0; a < 2; a++)
#pragma unroll
        for (int b = 0; b < 4; b++) acc[a][b] = 0ull;

    const float4* Wh4 = (const float4*)g_Wh;

    for (int j0 = 0; j0 < Lq; j0 += CJ) {
        // compute alpha chunk into smem
        {
            int j = j0 + jj_w;
            float4 s = __ldg(&sjg[j]);
            uint32_t sel = 1u << (j & 31);
            int wo = j >> 5;
#pragma unroll
            for (int k = 0; k < 4; k++) {
                int ii = iig * 4 + k;
                float w0 = 0.f, w1 = 0.f, w2 = 0.f, w3 = 0.f;
                if (mask_s[ii * 128 + wo] & sel) {
                    float4 si = si_s[ii], mm = m_s[ii], rd = rd_s[ii];
                    w0 = __expf(lrelu(si.x + s.x) - mm.x) * rd.x;
                    w1 = __expf(lrelu(si.y + s.y) - mm.y) * rd.y;
                    w2 = __expf(lrelu(si.z + s.z) - mm.z) * rd.z;
                    w3 = __expf(lrelu(si.w + s.w) - mm.w) * rd.w;
                }
                w_s[(0 * CJ + jj_w) * 34 + ii] = w0;
                w_s[(1 * CJ + jj_w) * 34 + ii] = w1;
                w_s[(2 * CJ + jj_w) * 34 + ii] = w2;
                w_s[(3 * CJ + jj_w) * 34 + ii] = w3;
            }
        }
        __syncthreads();

        const float*  wbase = w_s + hA * CJ * 34 + r0;
        const float4* whp   = Wh4 + (size_t)j0 * 64 + cq;
#pragma unroll 8
        for (int jj = 0; jj < CJ; jj++) {
            float4 wh = whp[(size_t)jj * 64];
            unsigned long long bx = pack2(wh.x, wh.x);
            unsigned long long by = pack2(wh.y, wh.y);
            unsigned long long bz = pack2(wh.z, wh.z);
            unsigned long long bw = pack2(wh.w, wh.w);
            const float* wp = wbase + jj * 34;
            unsigned long long w01 = *(const unsigned long long*)(wp + 0);
            unsigned long long w23 = *(const unsigned long long*)(wp + 2);
            fma2(acc[0][0], w01, bx); fma2(acc[0][1], w01, by);
            fma2(acc[0][2], w01, bz); fma2(acc[0][3], w01, bw);
            fma2(acc[1][0], w23, bx); fma2(acc[1][1], w23, by);
            fma2(acc[1][2], w23, bz); fma2(acc[1][3], w23, bw);
        }
        __syncthreads();
    }

    // writeback (unpack row pairs)
#pragma unroll
    for (int kp = 0; kp < 2; kp++) {
        float2 c0 = unpack2(acc[kp][0]);
        float2 c1 = unpack2(acc[kp][1]);
        float2 c2 = unpack2(acc[kp][2]);
        float2 c3 = unpack2(acc[kp][3]);
        int row = i0 + r0 + kp * 2;
        *(float4*)&g_att[(size_t)row * DOUTC + cq * 4] =
            make_float4(c0.x, c1.x, c2.x, c3.x);
        *(float4*)&g_att[(size_t)(row + 1) * DOUTC + cq * 4] =
            make_float4(c0.y, c1.y, c2.y, c3.y);
    }
}

// ---------------- launch ------------------------------------------------------
extern "C" void kernel_launch(void* const* d_in, const int* in_sizes, int n_in,
                              void* d_out, int out_size) {
    const float* h     = (const float*)d_in[0];
    const int*   A     = (const int*)d_in[1];
    const float* W     = (const float*)d_in[2];
    const float* attn  = (const float*)d_in[3];
    const float* out_w = (const float*)d_in[4];
    const float* out_b = (const float*)d_in[5];
    float*       out   = (float*)d_out;

    // 1) Wh = h @ W^T
    gemm64_nt<DIN, 0><<<dim3(DOUTC / 64, Lq / 64), 256>>>(h, W, nullptr, nullptr);
    // 2) s_i, s_j
    s_kernel<<<(Lq * NH) / 8, 256>>>(attn);
    // 3) masked softmax + aggregation
    cudaFuncSetAttribute(gat_attn_kernel,
                         cudaFuncAttributeMaxDynamicSharedMemorySize, SM_TOT);
    gat_attn_kernel<<<Lq / TI, 256, SM_TOT>>>(A);
    // 4) out = att @ out_w^T + out_b
    gemm64_nt<DOUTC, 1><<<dim3(DOUTC / 64, Lq / 64), 256>>>(nullptr, out_w, out, out_b);
}